// round 10
// baseline (speedup 1.0000x reference)
#include <cuda_runtime.h>

// Shape fixed by dataset: [B=2, 1, D=160, H=192, W=160] fp32.
#define DW 160
#define DH 192
#define DD 160
#define DB 2
#define PS (DH * DW)

#define CZ   16
#define NCHUNK (DD / CZ)          // 10
#define TY   8
#define TXN  40                   // 40*4 = 160 = full W
#define NT   320
#define SMS  168                  // 3 pad | halo | 160 | halo | 3 pad
#define SMROWS 10
#define PLANEF (SMROWS * SMS)
#define NS   3
#define NBLOCKS ((DH / TY) * DB * NCHUNK)   // 480

__device__ double       g_acc = 0.0;
__device__ unsigned int g_cnt = 0;

__global__ __launch_bounds__(NT, 3) void sobel_loss_kernel(
    const float* __restrict__ moved, const float* __restrict__ label,
    float* __restrict__ out)
{
    __shared__ __align__(16) float smd[NS][PLANEF];
    __shared__ float red[NT / 32];

    const int tid  = threadIdx.x;
    const int txi  = tid % TXN;
    const int tyi  = tid / TXN;
    const int lane = tid & 31;

    const int y0 = blockIdx.y * TY;
    const int b  = blockIdx.z / NCHUNK;
    const int z0 = (blockIdx.z % NCHUNK) * CZ;

    const size_t vol = (size_t)DD * PS;
    const float* mp = moved + (size_t)b * vol;
    const float* lp = label + (size_t)b * vol;

    const int  gy0  = y0 - 1 + tyi;
    const bool yv0  = (gy0 >= 0) && (gy0 < DH);
    const int  goff0 = (gy0 < 0 ? 0 : gy0) * DW + 4 * txi;
    const int  soff0 = tyi * SMS + 4 + 4 * txi;

    const bool kv1  = tid < (SMROWS * TXN - NT);   // tid < 80
    const int  k1   = tid + NT;
    const int  r1   = k1 / TXN;
    const int  c1   = k1 % TXN;
    const int  gy1  = y0 - 1 + r1;
    const bool yv1  = kv1 && (gy1 >= 0) && (gy1 < DH);
    const int  goff1 = (gy1 < 0 ? 0 : (gy1 >= DH ? DH - 1 : gy1)) * DW + 4 * c1;
    const int  soff1 = r1 * SMS + 4 + 4 * c1;

    if (tid < NS * SMROWS * 2) {          // zero x-halo cols once
        int side = tid & 1;
        int rest = tid >> 1;
        int rr = rest % SMROWS;
        int st = rest / SMROWS;
        smd[st][rr * SMS + (side ? 4 + DW : 3)] = 0.0f;
    }

    auto gload = [&](float4& va, float4& vb, int p) {
        const int z = z0 - 1 + p;
        va = make_float4(0.f, 0.f, 0.f, 0.f);
        vb = va;
        if (z >= 0 && z < DD) {
            const size_t zb = (size_t)z * PS;
            if (yv0) {
                float4 m = *(const float4*)(mp + zb + goff0);
                float4 l = *(const float4*)(lp + zb + goff0);
                va = make_float4(m.x - l.x, m.y - l.y, m.z - l.z, m.w - l.w);
            }
            if (yv1) {
                float4 m = *(const float4*)(mp + zb + goff1);
                float4 l = *(const float4*)(lp + zb + goff1);
                vb = make_float4(m.x - l.x, m.y - l.y, m.z - l.z, m.w - l.w);
            }
        }
    };
    auto sts = [&](int st, const float4& va, const float4& vb) {
        *(float4*)&smd[st][soff0] = va;
        if (kv1) *(float4*)&smd[st][soff1] = vb;
    };

    const bool fbL = (lane == 0)  || (txi == 0);
    const bool fbR = (lane == 31) || (txi == TXN - 1);

    float acc = 0.0f;
    float Agx[4], Agy[4], Agz[4], Bgx[4], Bgy[4], Bgz[4];
    #pragma unroll
    for (int j = 0; j < 4; ++j) {
        Agx[j] = Agy[j] = Agz[j] = 0.f;
        Bgx[j] = Bgy[j] = Bgz[j] = 0.f;
    }

    auto plane_step = [&](int cs, float* Pgx, float* Pgy, float* Pgz,
                          float* Qgx, float* Qgy, float* Qgz, bool emit) {
        const float* db = &smd[cs][tyi * SMS + 4 * txi];
        float sr[3][4], dr[3][4];
        #pragma unroll
        for (int rr = 0; rr < 3; ++rr) {
            const float* r = db + rr * SMS;
            float4 d4 = *(const float4*)(r + 4);
            float dl = __shfl_up_sync(0xffffffffu, d4.w, 1);
            float dR = __shfl_down_sync(0xffffffffu, d4.x, 1);
            if (fbL) dl = r[3];
            if (fbR) dR = r[8];
            sr[rr][0] = dl   + 2.f * d4.x + d4.y;  dr[rr][0] = d4.y - dl;
            sr[rr][1] = d4.x + 2.f * d4.y + d4.z;  dr[rr][1] = d4.z - d4.x;
            sr[rr][2] = d4.y + 2.f * d4.z + d4.w;  dr[rr][2] = d4.w - d4.y;
            sr[rr][3] = d4.z + 2.f * d4.w + dR;    dr[rr][3] = dR   - d4.z;
        }
        #pragma unroll
        for (int j = 0; j < 4; ++j) {
            float X = dr[0][j] + 2.f * dr[1][j] + dr[2][j];
            float S = sr[0][j] + 2.f * sr[1][j] + sr[2][j];
            float Y = sr[2][j] - sr[0][j];
            if (emit)
                acc += fabsf(Pgx[j] + X) + fabsf(Pgy[j] + Y) + fabsf(Pgz[j] + S);
            Qgx[j] += 2.f * X;
            Qgy[j] += 2.f * Y;
            Pgx[j] = X; Pgy[j] = Y; Pgz[j] = -S;
        }
    };

    float4 vA0, vA1, vB0, vB1;   // A: even planes, B: odd planes

    // ---- prologue ----
    gload(vA0, vA1, 0);                       // A = plane 0
    gload(vB0, vB1, 1);                       // B = plane 1
    sts(0, vA0, vA1);  gload(vA0, vA1, 2);    // stage0 = p0, A = plane 2
    sts(1, vB0, vB1);  gload(vB0, vB1, 3);    // stage1 = p1, B = plane 3
    __syncthreads();
    plane_step(0, Agx, Agy, Agz, Bgx, Bgy, Bgz, false);   // plane 0

    // p=1 step: sts plane 2 (even -> set A) into stage 2, prefetch plane 4 -> A
    sts(2, vA0, vA1);  gload(vA0, vA1, 4);
    __syncthreads();
    plane_step(1, Bgx, Bgy, Bgz, Agx, Agy, Agz, false);   // plane 1

    // ---- main loop: plane p emits center p-1; at p, sts plane p+1, prefetch p+3 ----
    #pragma unroll
    for (int p = 2; p <= CZ + 1; p += 2) {
        // even p: compute set P=A; plane p+1 is odd -> lives in B
        if (p + 1 <= CZ + 1) sts((p + 1) % NS, vB0, vB1);
        if (p + 3 <= CZ + 1) gload(vB0, vB1, p + 3);
        __syncthreads();
        plane_step(p % NS, Agx, Agy, Agz, Bgx, Bgy, Bgz, true);

        // odd p+1: compute set P=B; plane p+2 is even -> lives in A
        if (p + 2 <= CZ + 1) sts((p + 2) % NS, vA0, vA1);
        if (p + 4 <= CZ + 1) gload(vA0, vA1, p + 4);
        __syncthreads();
        plane_step((p + 1) % NS, Bgx, Bgy, Bgz, Agx, Agy, Agz, true);
    }

    // ---- reduction ----
    #pragma unroll
    for (int o = 16; o > 0; o >>= 1)
        acc += __shfl_down_sync(0xffffffffu, acc, o);
    if (lane == 0) red[tid >> 5] = acc;
    __syncthreads();

    if (tid == 0) {
        float s = 0.0f;
        #pragma unroll
        for (int i = 0; i < NT / 32; ++i) s += red[i];
        atomicAdd(&g_acc, (double)s);
        __threadfence();
        unsigned old = atomicInc(&g_cnt, NBLOCKS - 1);
        if (old == NBLOCKS - 1) {
            double total = atomicAdd(&g_acc, 0.0);
            out[0] = (float)(total / (3.0 * (double)DB * DD * DH * DW));
            g_acc = 0.0;
            __threadfence();
        }
    }
}

extern "C" void kernel_launch(void* const* d_in, const int* in_sizes, int n_in,
                              void* d_out, int out_size)
{
    (void)in_sizes; (void)n_in; (void)out_size;
    const float* moved = (const float*)d_in[0];
    const float* label = (const float*)d_in[1];
    float* out = (float*)d_out;

    dim3 grid(1, DH / TY, DB * NCHUNK);   // 480 blocks
    sobel_loss_kernel<<<grid, NT>>>(moved, label, out);
}

// round 12
// speedup vs baseline: 1.9835x; 1.9835x over previous
#include <cuda_runtime.h>

// Shape fixed by dataset: [B=2, 1, D=160, H=192, W=160] fp32.
#define DW 160
#define DH 192
#define DD 160
#define DB 2
#define PS (DH * DW)

#define CZ   20                   // z-outputs per block
#define NCHUNK (DD / CZ)          // 8
#define TY   8
#define TXN  40                   // 40*4 = 160 = full W
#define NT   320
#define SMS  168                  // 3 pad | halo | 160 | halo | 3 pad
#define SMROWS 10
#define PLANEF (SMROWS * SMS)
#define NS   2
#define NBLOCKS ((DH / TY) * DB * NCHUNK)   // 24*2*8 = 384 (single wave @ occ 3)

__device__ double       g_acc = 0.0;
__device__ unsigned int g_cnt = 0;

__global__ __launch_bounds__(NT, 3) void sobel_loss_kernel(
    const float* __restrict__ moved, const float* __restrict__ label,
    float* __restrict__ out)
{
    __shared__ __align__(16) float smd[NS][PLANEF];
    __shared__ float red[NT / 32];

    const int tid  = threadIdx.x;
    const int txi  = tid % TXN;
    const int tyi  = tid / TXN;
    const int lane = tid & 31;

    const int y0 = blockIdx.y * TY;
    const int b  = blockIdx.z / NCHUNK;
    const int z0 = (blockIdx.z % NCHUNK) * CZ;

    const size_t vol = (size_t)DD * PS;
    const float* mp = moved + (size_t)b * vol;
    const float* lp = label + (size_t)b * vol;

    // load slot 0: halo-window row tyi (rows 0..7)
    const int  gy0  = y0 - 1 + tyi;
    const bool yv0  = (gy0 >= 0) && (gy0 < DH);
    const int  goff0 = (gy0 < 0 ? 0 : gy0) * DW + 4 * txi;
    const int  soff0 = tyi * SMS + 4 + 4 * txi;
    // load slot 1: rows 8,9 (tid < 80)
    const bool kv1  = tid < (SMROWS * TXN - NT);
    const int  k1   = tid + NT;
    const int  r1   = k1 / TXN;
    const int  c1   = k1 % TXN;
    const int  gy1  = y0 - 1 + r1;
    const bool yv1  = kv1 && (gy1 >= 0) && (gy1 < DH);
    const int  goff1 = (gy1 < 0 ? 0 : (gy1 >= DH ? DH - 1 : gy1)) * DW + 4 * c1;
    const int  soff1 = r1 * SMS + 4 + 4 * c1;

    // zero the x-halo columns (idx 3 and 164) of both buffers, once
    if (tid < NS * SMROWS * 2) {          // 40 threads
        int side = tid & 1;
        int rest = tid >> 1;
        int rr = rest % SMROWS;
        int st = rest / SMROWS;
        smd[st][rr * SMS + (side ? 4 + DW : 3)] = 0.0f;
    }

    float4 v0, v1;   // single prefetch set: freed at STS issue, reloaded immediately

    auto gload = [&](int p) {            // plane p: z = z0-1+p, zero outside volume
        const int z = z0 - 1 + p;
        v0 = make_float4(0.f, 0.f, 0.f, 0.f);
        v1 = v0;
        if (z >= 0 && z < DD) {
            const size_t zb = (size_t)z * PS;
            if (yv0) {
                float4 m = *(const float4*)(mp + zb + goff0);
                float4 l = *(const float4*)(lp + zb + goff0);
                v0 = make_float4(m.x - l.x, m.y - l.y, m.z - l.z, m.w - l.w);
            }
            if (yv1) {
                float4 m = *(const float4*)(mp + zb + goff1);
                float4 l = *(const float4*)(lp + zb + goff1);
                v1 = make_float4(m.x - l.x, m.y - l.y, m.z - l.z, m.w - l.w);
            }
        }
    };
    auto sts = [&](int st) {
        *(float4*)&smd[st][soff0] = v0;
        if (kv1) *(float4*)&smd[st][soff1] = v1;
    };

    const bool fbL = (lane == 0)  || (txi == 0);
    const bool fbR = (lane == 31) || (txi == TXN - 1);

    float acc = 0.0f;
    // two-in-flight accumulators: A handles one output parity, B the other
    float Agx[4], Agy[4], Agz[4], Bgx[4], Bgy[4], Bgz[4];
    #pragma unroll
    for (int j = 0; j < 4; ++j) {
        Agx[j] = Agy[j] = Agz[j] = 0.f;
        Bgx[j] = Bgy[j] = Bgz[j] = 0.f;
    }

    // per-plane separable partials (X=Sy(Dx), Y=Dy(Sx), S=Sy(Sx)) + accumulate.
    // At plane p: emit output centered p-1 from slot P, add 2x to slot Q
    // (output centered p), reset P for output centered p+1.
    auto plane_step = [&](int cs, float* Pgx, float* Pgy, float* Pgz,
                          float* Qgx, float* Qgy, float* Qgz, bool emit) {
        const float* db = &smd[cs][tyi * SMS + 4 * txi];
        float X[4], S[4], Y[4];
        #pragma unroll
        for (int rr = 0; rr < 3; ++rr) {
            const float* r = db + rr * SMS;
            float4 d4 = *(const float4*)(r + 4);
            float dl = __shfl_up_sync(0xffffffffu, d4.w, 1);
            float dR = __shfl_down_sync(0xffffffffu, d4.x, 1);
            if (fbL) dl = r[3];          // zero-padded halo / row-break fallback
            if (fbR) dR = r[8];
            float s0 = dl   + 2.f * d4.x + d4.y,  e0 = d4.y - dl;
            float s1 = d4.x + 2.f * d4.y + d4.z,  e1 = d4.z - d4.x;
            float s2 = d4.y + 2.f * d4.z + d4.w,  e2 = d4.w - d4.y;
            float s3 = d4.z + 2.f * d4.w + dR,    e3 = dR   - d4.z;
            if (rr == 0) {
                X[0] = e0; X[1] = e1; X[2] = e2; X[3] = e3;
                S[0] = s0; S[1] = s1; S[2] = s2; S[3] = s3;
                Y[0] = -s0; Y[1] = -s1; Y[2] = -s2; Y[3] = -s3;
            } else if (rr == 1) {
                X[0] += 2.f * e0; X[1] += 2.f * e1; X[2] += 2.f * e2; X[3] += 2.f * e3;
                S[0] += 2.f * s0; S[1] += 2.f * s1; S[2] += 2.f * s2; S[3] += 2.f * s3;
            } else {
                X[0] += e0; X[1] += e1; X[2] += e2; X[3] += e3;
                S[0] += s0; S[1] += s1; S[2] += s2; S[3] += s3;
                Y[0] += s0; Y[1] += s1; Y[2] += s2; Y[3] += s3;
            }
        }
        #pragma unroll
        for (int j = 0; j < 4; ++j) {
            if (emit)
                acc += fabsf(Pgx[j] + X[j]) + fabsf(Pgy[j] + Y[j]) + fabsf(Pgz[j] + S[j]);
            Qgx[j] += 2.f * X[j];
            Qgy[j] += 2.f * Y[j];
            Pgx[j] = X[j]; Pgy[j] = Y[j]; Pgz[j] = -S[j];
        }
    };

    // ---- prologue: planes 0,1 (no emit) ----
    gload(0);
    sts(0);  gload(1);
    __syncthreads();
    plane_step(0, Agx, Agy, Agz, Bgx, Bgy, Bgz, false);

    sts(1);  gload(2);
    __syncthreads();
    plane_step(1, Bgx, Bgy, Bgz, Agx, Agy, Agz, false);

    // ---- main: planes 2..CZ+1, one barrier per plane ----
    #pragma unroll 1
    for (int p = 2; p <= CZ; p += 2) {
        sts(0);  gload(p + 1);                 // even plane p -> buf 0
        __syncthreads();
        plane_step(0, Agx, Agy, Agz, Bgx, Bgy, Bgz, true);

        sts(1);  gload(p + 2);                 // odd plane p+1 -> buf 1
        __syncthreads();
        plane_step(1, Bgx, Bgy, Bgz, Agx, Agy, Agz, true);
    }

    // ---- reduction ----
    #pragma unroll
    for (int o = 16; o > 0; o >>= 1)
        acc += __shfl_down_sync(0xffffffffu, acc, o);
    if (lane == 0) red[tid >> 5] = acc;
    __syncthreads();

    if (tid == 0) {
        float s = 0.0f;
        #pragma unroll
        for (int i = 0; i < NT / 32; ++i) s += red[i];
        atomicAdd(&g_acc, (double)s);
        __threadfence();
        unsigned old = atomicInc(&g_cnt, NBLOCKS - 1);
        if (old == NBLOCKS - 1) {
            double total = atomicAdd(&g_acc, 0.0);
            out[0] = (float)(total / (3.0 * (double)DB * DD * DH * DW));
            g_acc = 0.0;
            __threadfence();
        }
    }
}

extern "C" void kernel_launch(void* const* d_in, const int* in_sizes, int n_in,
                              void* d_out, int out_size)
{
    (void)in_sizes; (void)n_in; (void)out_size;
    const float* moved = (const float*)d_in[0];
    const float* label = (const float*)d_in[1];
    float* out = (float*)d_out;

    dim3 grid(1, DH / TY, DB * NCHUNK);   // (1, 24, 16) = 384 blocks
    sobel_loss_kernel<<<grid, NT>>>(moved, label, out);
}